// round 9
// baseline (speedup 1.0000x reference)
#include <cuda_runtime.h>
#include <cuda_fp16.h>
#include <cstdint>

// ============================================================================
// Scratch (static __device__ arrays — no allocations allowed)
// ============================================================================
#define KROWS 8192
#define NROWS 8192
#define MDIM  64
#define NSPLIT 8

__device__ uint8_t g_Xq[KROWS * MDIM];      // (2*log2e) * x, e4m3
__device__ uint8_t g_Cq[NROWS * MDIM];      // x_basis, e4m3
__device__ float   g_xsf[KROWS];            // -log2e * ||x_i||^2
__device__ float   g_csf[NROWS];            // -log2e * ||c_j||^2
__device__ __half  g_wh[NROWS];             // w_j (f16)
__device__ float   g_partial[NSPLIT][KROWS];

#define LOG2E 1.4426950408889634f

// ============================================================================
// PTX helpers (baseline features only — sm_100 non-'a' target)
// ============================================================================
__device__ __forceinline__ uint32_t smem_u32(const void* p) {
    uint32_t a;
    asm("{ .reg .u64 t; cvta.to.shared.u64 t, %1; cvt.u32.u64 %0, t; }"
        : "=r"(a) : "l"(p));
    return a;
}

// fp8 e4m3 x e4m3 -> f32 accumulate, K=32 per instruction
__device__ __forceinline__ void mma16832_fp8(float* c, const uint32_t* a,
                                             uint32_t b0, uint32_t b1) {
    asm volatile(
        "mma.sync.aligned.m16n8k32.row.col.f32.e4m3.e4m3.f32 "
        "{%0,%1,%2,%3}, {%4,%5,%6,%7}, {%8,%9}, {%0,%1,%2,%3};"
        : "+f"(c[0]), "+f"(c[1]), "+f"(c[2]), "+f"(c[3])
        : "r"(a[0]), "r"(a[1]), "r"(a[2]), "r"(a[3]), "r"(b0), "r"(b1));
}

__device__ __forceinline__ void ldsm_x4(uint32_t addr, uint32_t* r) {
    asm volatile("ldmatrix.sync.aligned.m8n8.x4.shared.b16 {%0,%1,%2,%3}, [%4];"
                 : "=r"(r[0]), "=r"(r[1]), "=r"(r[2]), "=r"(r[3]) : "r"(addr));
}

#define CP_ASYNC16(dst, src) \
    asm volatile("cp.async.cg.shared.global [%0], [%1], 16;" :: "r"(dst), "l"(src))
#define CP_COMMIT() asm volatile("cp.async.commit_group;" ::: "memory")
#define CP_WAIT0()  asm volatile("cp.async.wait_group 0;" ::: "memory")

// two f32 -> f16x2 (lo = t0), then packed exp2
__device__ __forceinline__ uint32_t ex2_pair(float t0, float t1) {
    uint32_t h, e;
    asm("cvt.rn.f16x2.f32 %0, %1, %2;" : "=r"(h) : "f"(t1), "f"(t0));
    asm("ex2.approx.f16x2 %0, %1;" : "=r"(e) : "r"(h));
    return e;
}

// ============================================================================
// K1: quantize to e4m3 (x pre-scaled by 2*log2e), f32 norms, cs/w pack
// 16 threads per row, float4 each; 16384 rows total
// ============================================================================
__global__ void prep_kernel(const float* __restrict__ x,
                            const float* __restrict__ xb,
                            const float* __restrict__ w) {
    int idx   = blockIdx.x * 256 + threadIdx.x;
    int row16 = idx >> 4;                 // 0..16383
    int s     = idx & 15;
    bool isb  = row16 >= KROWS;
    int r     = isb ? row16 - KROWS : row16;
    const float* src = isb ? xb : x;

    float4 v = ((const float4*)(src + (size_t)r * MDIM))[s];
    const float sc = isb ? 1.0f : (2.0f * LOG2E);   // pre-scale x only
    uint16_t q01, q23;
    asm("cvt.rn.satfinite.e4m3x2.f32 %0, %1, %2;"
        : "=h"(q01) : "f"(sc * v.y), "f"(sc * v.x));
    asm("cvt.rn.satfinite.e4m3x2.f32 %0, %1, %2;"
        : "=h"(q23) : "f"(sc * v.w), "f"(sc * v.z));
    uint32_t q = (uint32_t)q01 | ((uint32_t)q23 << 16);
    uint8_t* dst = isb ? g_Cq : g_Xq;
    ((uint32_t*)(dst + (size_t)r * MDIM))[s] = q;

    float nrm = v.x * v.x + v.y * v.y + v.z * v.z + v.w * v.w;
    #pragma unroll
    for (int o = 8; o; o >>= 1) nrm += __shfl_xor_sync(0xFFFFFFFFu, nrm, o);

    if (s == 0) {
        float e = -LOG2E * nrm;
        if (isb) {
            g_csf[r] = e;
            g_wh[r]  = __float2half(w[r]);
        } else {
            g_xsf[r] = e;
        }
    }
}

// ============================================================================
// K2: smem-staged FP8 GEMM (m16n8k32, f32 accum preloaded with xs+cs)
//     + ex2.f16x2 / hfma2 epilogue
// grid = (64 i-tiles, 8 j-splits) = 512 CTAs, 256 threads = 8 warps
// warp grid: 4 warp-rows (32 A-rows) x 2 warp-cols (64 B-cols)
// Tiles: 128 rows x 64 B data in 128 B pitch, xor-swizzled (8 KB data / 16 KB)
// ============================================================================
#define TI 128
#define TJ 128
#define TPC 8               // j-tiles per CTA: 8192/8/128
#define TILE_BYTES 16384    // 128 rows x 128 B pitch

// swizzled address of 16B chunk (row, ch) — ch in 0..3 (64B data per row)
__device__ __forceinline__ uint32_t tile_addr(uint32_t base, int row, int ch) {
    return base + (row << 7) + (((uint32_t)(ch ^ (row & 7))) << 4);
}

// stage one 128x64B fp8 tile: 512 16B-chunks, 2 cp.async per thread
__device__ __forceinline__ void stage_tile(uint32_t sdst,
                                           const uint8_t* gsrc, int tid) {
    #pragma unroll
    for (int p = 0; p < 2; p++) {
        int c   = tid + (p << 8);            // 0..511
        int row = c >> 2, ch = c & 3;
        uint32_t dst = tile_addr(sdst, row, ch);
        const char* src = (const char*)gsrc + (row << 6) + (ch << 4);
        CP_ASYNC16(dst, src);
    }
}

__global__ void __launch_bounds__(256, 2) rbf_main_kernel() {
    __shared__ __align__(1024) uint8_t bufs[2][TILE_BYTES];   // 32 KB
    __shared__ float red[2][TI];

    const int tid = threadIdx.x;
    const int wid = tid >> 5;
    const int lid = tid & 31;
    const int wrow = wid >> 1;           // 0..3 (32-row slice of A)
    const int wc   = wid & 1;            // 0..1 (64-col slice of B)
    const int g    = lid >> 2;           // 0..7
    const int q2   = (lid & 3) * 2;      // 0,2,4,6

    const int i0    = blockIdx.x * TI;
    const int js    = blockIdx.y;
    const int jbase = js * (TJ * TPC);

    const uint32_t sbuf0 = smem_u32(bufs[0]);
    const uint32_t sbuf1 = smem_u32(bufs[1]);

    // ---- stage A into buf1, B tile 0 into buf0 ----
    stage_tile(sbuf1, g_Xq + (size_t)i0 * MDIM, tid);
    stage_tile(sbuf0, g_Cq + (size_t)jbase * MDIM, tid);
    CP_COMMIT();
    CP_WAIT0();
    __syncthreads();

    // ---- persistent A fragments from buf1 via ldmatrix (byte-compatible) ----
    uint32_t a[2][2][4];                 // [mt][ks], ks covers k32 each
    {
        const int arow_lo = (lid & 7) + ((lid >> 3) & 1) * 8;
        const int chsel   = lid >> 4;                  // 16B half of the k32
        #pragma unroll
        for (int mt = 0; mt < 2; mt++) {
            #pragma unroll
            for (int ks = 0; ks < 2; ks++) {
                int row = wrow * 32 + mt * 16 + arow_lo;
                ldsm_x4(tile_addr(sbuf1, row, ks * 2 + chsel), a[mt][ks]);
            }
        }
    }
    __syncthreads();     // A reads done before buf1 reused for B(1)

    // per-thread row exponents (f32)
    float xs[2][2];
    #pragma unroll
    for (int mt = 0; mt < 2; mt++)
        #pragma unroll
        for (int h = 0; h < 2; h++)
            xs[mt][h] = g_xsf[i0 + wrow * 32 + mt * 16 + g + h * 8];

    __half2 acc2[2][2];
    #pragma unroll
    for (int mt = 0; mt < 2; mt++)
        #pragma unroll
        for (int h = 0; h < 2; h++) acc2[mt][h] = __float2half2_rn(0.f);

    // B-ldmatrix lane addressing: matrix m = lid>>3; octet (m>>1), chunk (m&1)
    const int brow_lo = wc * 64 + ((lid >> 4) << 3) + (lid & 7);
    const int bch_lo  = (lid >> 3) & 1;

    for (int t = 0; t < TPC; t++) {
        if (t + 1 < TPC) {
            uint32_t nb = (t & 1) ? sbuf0 : sbuf1;
            stage_tile(nb, g_Cq + (size_t)(jbase + (t + 1) * TJ) * MDIM, tid);
            CP_COMMIT();
        }
        const uint32_t sb = (t & 1) ? sbuf1 : sbuf0;

        // process the warp's 64 cols in two 32-col halves (bounds f32 regs)
        #pragma unroll
        for (int half = 0; half < 2; half++) {
            const int j0h = jbase + t * TJ + wc * 64 + half * 32;

            // cs (f32 pairs) + w (f16 pairs) for 4 col-octets
            float2  cs2[4];
            __half2 w2[4];
            #pragma unroll
            for (int nt = 0; nt < 4; nt++) {
                const int jj = j0h + nt * 8 + q2;
                cs2[nt] = *(const float2*)(g_csf + jj);
                w2[nt]  = *(const __half2*)(g_wh + jj);
            }

            // accumulator preload: C = xs_row + cs_col (MMA adds C2*S)
            float c[2][4][4];
            #pragma unroll
            for (int mt = 0; mt < 2; mt++)
                #pragma unroll
                for (int nt = 0; nt < 4; nt++) {
                    c[mt][nt][0] = xs[mt][0] + cs2[nt].x;
                    c[mt][nt][1] = xs[mt][0] + cs2[nt].y;
                    c[mt][nt][2] = xs[mt][1] + cs2[nt].x;
                    c[mt][nt][3] = xs[mt][1] + cs2[nt].y;
                }

            #pragma unroll
            for (int ks = 0; ks < 2; ks++) {
                uint32_t b[4][2];
                #pragma unroll
                for (int ga = 0; ga < 2; ga++) {
                    int row = brow_lo + half * 32 + ga * 16;
                    uint32_t r[4];
                    ldsm_x4(tile_addr(sb, row, ks * 2 + bch_lo), r);
                    b[ga * 2 + 0][0] = r[0]; b[ga * 2 + 0][1] = r[1];
                    b[ga * 2 + 1][0] = r[2]; b[ga * 2 + 1][1] = r[3];
                }
                #pragma unroll
                for (int nt = 0; nt < 4; nt++) {
                    mma16832_fp8(c[0][nt], a[0][ks], b[nt][0], b[nt][1]);
                    mma16832_fp8(c[1][nt], a[1][ks], b[nt][0], b[nt][1]);
                }
            }

            // epilogue: acc += w * 2^(c)   (c = C2*S + xs + cs <= 0)
            #pragma unroll
            for (int nt = 0; nt < 4; nt++) {
                #pragma unroll
                for (int mt = 0; mt < 2; mt++) {
                    uint32_t e0 = ex2_pair(c[mt][nt][0], c[mt][nt][1]);
                    uint32_t e1 = ex2_pair(c[mt][nt][2], c[mt][nt][3]);
                    acc2[mt][0] = __hfma2(*(const __half2*)&e0, w2[nt], acc2[mt][0]);
                    acc2[mt][1] = __hfma2(*(const __half2*)&e1, w2[nt], acc2[mt][1]);
                }
            }
        }

        if (t + 1 < TPC) CP_WAIT0();
        __syncthreads();
    }

    // ---- reduce: cols within quad, then across warp-cols via smem ----
    float accf[2][2];
    #pragma unroll
    for (int mt = 0; mt < 2; mt++)
        #pragma unroll
        for (int h = 0; h < 2; h++) {
            float v = __low2float(acc2[mt][h]) + __high2float(acc2[mt][h]);
            v += __shfl_xor_sync(0xFFFFFFFFu, v, 1);
            v += __shfl_xor_sync(0xFFFFFFFFu, v, 2);
            accf[mt][h] = v;
        }

    if ((lid & 3) == 0) {
        #pragma unroll
        for (int mt = 0; mt < 2; mt++)
            #pragma unroll
            for (int h = 0; h < 2; h++)
                red[wc][wrow * 32 + mt * 16 + g + h * 8] = accf[mt][h];
    }
    __syncthreads();
    if (tid < TI)
        g_partial[js][i0 + tid] = red[0][tid] + red[1][tid];
}

// ============================================================================
// K3: combine partials + bias + sigmoid
// ============================================================================
__global__ void finish_kernel(const float* __restrict__ b, float* __restrict__ out) {
    int i = blockIdx.x * 256 + threadIdx.x;
    float z = b[0];
    #pragma unroll
    for (int s = 0; s < NSPLIT; s++) z += g_partial[s][i];
    out[i] = 1.0f / (1.0f + __expf(-z));
}

// ============================================================================
// kernel_launch
// ============================================================================
extern "C" void kernel_launch(void* const* d_in, const int* in_sizes, int n_in,
                              void* d_out, int out_size) {
    const float* x  = (const float*)d_in[0];
    const float* xb = (const float*)d_in[1];
    const float* w  = (const float*)d_in[2];
    const float* b  = (const float*)d_in[3];
    float* out = (float*)d_out;

    prep_kernel<<<1024, 256>>>(x, xb, w);
    dim3 grid(KROWS / TI, NSPLIT);
    rbf_main_kernel<<<grid, 256>>>();
    finish_kernel<<<KROWS / 256, 256>>>(b, out);
}

// round 10
// speedup vs baseline: 1.3470x; 1.3470x over previous
#include <cuda_runtime.h>
#include <cuda_fp16.h>
#include <cstdint>

// ============================================================================
// Scratch (static __device__ arrays — no allocations allowed)
// ============================================================================
#define KROWS 8192
#define NROWS 8192
#define MDIM  64
#define NSPLIT 4

__device__ __half g_Xh[KROWS * MDIM];       // x in f16
__device__ __half g_Ch[NROWS * MDIM];       // x_basis in f16
__device__ __half g_xsh[KROWS];             // -log2e * ||x_i||^2  (f16)
__device__ __half g_csh[NROWS];             // -log2e * ||c_j||^2  (f16)
__device__ __half g_wh[NROWS];              // w_j                 (f16)
__device__ float  g_partial[NSPLIT][KROWS]; // j-split partial logits
__device__ int    g_arrive[KROWS / 128];    // per-i-tile arrival counters (0-init)

#define LOG2E 1.4426950408889634f

// ============================================================================
// PTX helpers (baseline features only — sm_100 non-'a' target)
// ============================================================================
__device__ __forceinline__ uint32_t smem_u32(const void* p) {
    uint32_t a;
    asm("{ .reg .u64 t; cvta.to.shared.u64 t, %1; cvt.u32.u64 %0, t; }"
        : "=r"(a) : "l"(p));
    return a;
}

// f16 x f16 -> f16 accumulate (2x rate vs f32 accum)
__device__ __forceinline__ void mma16816_f16(uint32_t& c0, uint32_t& c1,
                                             const uint32_t* a,
                                             uint32_t b0, uint32_t b1) {
    asm volatile(
        "mma.sync.aligned.m16n8k16.row.col.f16.f16.f16.f16 "
        "{%0,%1}, {%2,%3,%4,%5}, {%6,%7}, {%0,%1};"
        : "+r"(c0), "+r"(c1)
        : "r"(a[0]), "r"(a[1]), "r"(a[2]), "r"(a[3]), "r"(b0), "r"(b1));
}

__device__ __forceinline__ void ldsm_x4(uint32_t addr, uint32_t* r) {
    asm volatile("ldmatrix.sync.aligned.m8n8.x4.shared.b16 {%0,%1,%2,%3}, [%4];"
                 : "=r"(r[0]), "=r"(r[1]), "=r"(r[2]), "=r"(r[3]) : "r"(addr));
}

#define CP_ASYNC16(dst, src) \
    asm volatile("cp.async.cg.shared.global [%0], [%1], 16;" :: "r"(dst), "l"(src))
#define CP_COMMIT() asm volatile("cp.async.commit_group;" ::: "memory")
#define CP_WAIT0()  asm volatile("cp.async.wait_group 0;" ::: "memory")

__device__ __forceinline__ uint32_t ex2_h2(uint32_t t) {
    uint32_t e;
    asm("ex2.approx.f16x2 %0, %1;" : "=r"(e) : "r"(t));
    return e;
}

// ============================================================================
// K1: convert to f16, norms, cs/w pack
// 512 blocks x 256 threads; 8 threads/row, 2 independent float4 each (MLP=2)
// ============================================================================
__global__ void prep_kernel(const float* __restrict__ x,
                            const float* __restrict__ xb,
                            const float* __restrict__ w) {
    int idx  = blockIdx.x * 256 + threadIdx.x;
    int row8 = idx >> 3;                  // 0..16383
    int s    = idx & 7;
    bool isb = row8 >= KROWS;
    int r    = isb ? row8 - KROWS : row8;
    const float* src = isb ? xb : x;

    const float4* rp = (const float4*)(src + (size_t)r * MDIM);
    float4 v0 = rp[s];
    float4 v1 = rp[s + 8];

    __half2 a01 = __floats2half2_rn(v0.x, v0.y);
    __half2 a23 = __floats2half2_rn(v0.z, v0.w);
    __half2 b01 = __floats2half2_rn(v1.x, v1.y);
    __half2 b23 = __floats2half2_rn(v1.z, v1.w);
    __half* dst = isb ? g_Ch : g_Xh;
    uint2* dp = (uint2*)(dst + (size_t)r * MDIM);
    uint2 p0, p1;
    p0.x = *(const uint32_t*)&a01; p0.y = *(const uint32_t*)&a23;
    p1.x = *(const uint32_t*)&b01; p1.y = *(const uint32_t*)&b23;
    dp[s]     = p0;
    dp[s + 8] = p1;

    float nrm = v0.x * v0.x + v0.y * v0.y + v0.z * v0.z + v0.w * v0.w
              + v1.x * v1.x + v1.y * v1.y + v1.z * v1.z + v1.w * v1.w;
    #pragma unroll
    for (int o = 4; o; o >>= 1) nrm += __shfl_xor_sync(0xFFFFFFFFu, nrm, o);

    if (s == 0) {
        float e = -LOG2E * nrm;
        if (isb) {
            g_csh[r] = __float2half(e);
            g_wh[r]  = __float2half(w[r]);
        } else {
            g_xsh[r] = __float2half(e);
        }
    }
}

// ============================================================================
// K2: smem-staged f16 GEMM (mma.sync f16-accum + ldmatrix + cp.async)
//     + fused f16x2 exp/weighted-sum epilogue + fused finish (last-CTA)
// grid = (64 i-tiles, 4 j-splits) = 256 CTAs, 256 threads = 8 warps
// warp grid: 4 warp-rows (32 A-rows) x 2 warp-cols (64 B-cols)
// ============================================================================
#define TI 128
#define TJ 128
#define TPC 16              // j-tiles per CTA: 8192/4/128
#define TILE_BYTES 16384    // 128 rows x 128 B (64 f16)

__device__ __forceinline__ void stage_tile(uint32_t sdst,
                                           const __half* gsrc, int tid) {
    #pragma unroll
    for (int p = 0; p < 4; p++) {
        int c   = tid + (p << 8);            // 0..1023 16B-chunks
        int row = c >> 3, ch = c & 7;
        uint32_t dst = sdst + (row << 7) + ((ch ^ (row & 7)) << 4);
        const char* src = (const char*)gsrc + (row << 7) + (ch << 4);
        CP_ASYNC16(dst, src);
    }
}

__global__ void __launch_bounds__(256, 2) rbf_main_kernel(
        const float* __restrict__ bias, float* __restrict__ out) {
    __shared__ __align__(1024) uint8_t bufs[2][TILE_BYTES];   // 32 KB
    __shared__ float red[2][TI];
    __shared__ int is_last;

    const int tid = threadIdx.x;
    const int wid = tid >> 5;
    const int lid = tid & 31;
    const int wrow = wid >> 1;           // 0..3 (32-row slice of A)
    const int wc   = wid & 1;            // 0..1 (64-col slice of B)
    const int g    = lid >> 2;           // 0..7
    const int q2   = (lid & 3) * 2;      // 0,2,4,6

    const int i0    = blockIdx.x * TI;
    const int js    = blockIdx.y;
    const int jbase = js * (TJ * TPC);

    const uint32_t sbuf0 = smem_u32(bufs[0]);
    const uint32_t sbuf1 = smem_u32(bufs[1]);

    // ---- stage A into buf1, B tile 0 into buf0 ----
    stage_tile(sbuf1, g_Xh + (size_t)i0 * MDIM, tid);
    stage_tile(sbuf0, g_Ch + (size_t)jbase * MDIM, tid);
    CP_COMMIT();
    CP_WAIT0();
    __syncthreads();

    // ---- persistent A fragments from buf1 via ldmatrix ----
    uint32_t a[2][4][4];                 // [mt][ks][reg]
    {
        const int arow_lo = (lid & 7) + ((lid >> 3) & 1) * 8;
        const int chsel   = lid >> 4;
        #pragma unroll
        for (int mt = 0; mt < 2; mt++) {
            #pragma unroll
            for (int ks = 0; ks < 4; ks++) {
                int row = wrow * 32 + mt * 16 + arow_lo;
                int ch  = ks * 2 + chsel;
                uint32_t addr = sbuf1 + (row << 7) + ((ch ^ (row & 7)) << 4);
                ldsm_x4(addr, a[mt][ks]);
            }
        }
    }
    __syncthreads();     // A reads done before buf1 reused for B(1)

    // per-thread row exponent broadcasts (f16x2)
    uint32_t xsb[2][2];
    #pragma unroll
    for (int mt = 0; mt < 2; mt++)
        #pragma unroll
        for (int h = 0; h < 2; h++) {
            __half2 b2 = __half2half2(g_xsh[i0 + wrow * 32 + mt * 16 + g + h * 8]);
            xsb[mt][h] = *(const uint32_t*)&b2;
        }

    const __half2 C2h = __float2half2_rn(2.0f * LOG2E);
    const uint32_t C2u = *(const uint32_t*)&C2h;

    __half2 acc2[2][2];
    #pragma unroll
    for (int mt = 0; mt < 2; mt++)
        #pragma unroll
        for (int h = 0; h < 2; h++) acc2[mt][h] = __float2half2_rn(0.f);

    // B-ldmatrix lane addressing: matrix m = lid>>3, row-octet (m>>1)
    const int brow_lo = wc * 64 + ((lid >> 4) << 3) + (lid & 7);
    const int bch_lo  = (lid >> 3) & 1;

    for (int t = 0; t < TPC; t++) {
        if (t + 1 < TPC) {
            uint32_t nb = (t & 1) ? sbuf0 : sbuf1;
            stage_tile(nb, g_Ch + (size_t)(jbase + (t + 1) * TJ) * MDIM, tid);
            CP_COMMIT();
        }
        const uint32_t sb = (t & 1) ? sbuf1 : sbuf0;
        const int j0 = jbase + t * TJ + wc * 64;

        // ---- MMA: 2 mt x 8 nt, f16 accumulate ----
        uint32_t c[2][8][2];
        #pragma unroll
        for (int mt = 0; mt < 2; mt++)
            #pragma unroll
            for (int nt = 0; nt < 8; nt++) { c[mt][nt][0] = 0u; c[mt][nt][1] = 0u; }

        #pragma unroll
        for (int ks = 0; ks < 4; ks++) {
            uint32_t b[8][2];
            #pragma unroll
            for (int ga = 0; ga < 4; ga++) {
                int row = brow_lo + ga * 16;
                int ch  = ks * 2 + bch_lo;
                uint32_t addr = sb + (row << 7) + ((ch ^ (row & 7)) << 4);
                uint32_t r[4]; ldsm_x4(addr, r);
                b[ga * 2 + 0][0] = r[0]; b[ga * 2 + 0][1] = r[1];
                b[ga * 2 + 1][0] = r[2]; b[ga * 2 + 1][1] = r[3];
            }
            #pragma unroll
            for (int nt = 0; nt < 8; nt++) {
                mma16816_f16(c[0][nt][0], c[0][nt][1], a[0][ks], b[nt][0], b[nt][1]);
                mma16816_f16(c[1][nt][0], c[1][nt][1], a[1][ks], b[nt][0], b[nt][1]);
            }
        }

        // ---- epilogue (all f16x2): acc += w * 2^(C2*S + xs + cs) ----
        #pragma unroll
        for (int nt = 0; nt < 8; nt++) {
            const int jj = j0 + nt * 8 + q2;
            const uint32_t cs2 = *(const uint32_t*)(g_csh + jj);
            const uint32_t w2  = *(const uint32_t*)(g_wh + jj);
            const __half2 cs2h = *(const __half2*)&cs2;
            const __half2 w2h  = *(const __half2*)&w2;
            #pragma unroll
            for (int mt = 0; mt < 2; mt++) {
                #pragma unroll
                for (int h = 0; h < 2; h++) {
                    __half2 base = __hadd2(*(const __half2*)&xsb[mt][h], cs2h);
                    __half2 cc   = *(const __half2*)&c[mt][nt][h];
                    __half2 t2   = __hfma2(cc, *(const __half2*)&C2u, base);
                    uint32_t e   = ex2_h2(*(const uint32_t*)&t2);
                    acc2[mt][h]  = __hfma2(*(const __half2*)&e, w2h, acc2[mt][h]);
                }
            }
        }

        if (t + 1 < TPC) CP_WAIT0();
        __syncthreads();
    }

    // ---- reduce: cols within quad, then across warp-cols via smem ----
    float accf[2][2];
    #pragma unroll
    for (int mt = 0; mt < 2; mt++)
        #pragma unroll
        for (int h = 0; h < 2; h++) {
            float v = __low2float(acc2[mt][h]) + __high2float(acc2[mt][h]);
            v += __shfl_xor_sync(0xFFFFFFFFu, v, 1);
            v += __shfl_xor_sync(0xFFFFFFFFu, v, 2);
            accf[mt][h] = v;
        }

    if ((lid & 3) == 0) {
        #pragma unroll
        for (int mt = 0; mt < 2; mt++)
            #pragma unroll
            for (int h = 0; h < 2; h++)
                red[wc][wrow * 32 + mt * 16 + g + h * 8] = accf[mt][h];
    }
    __syncthreads();
    if (tid < TI)
        g_partial[js][i0 + tid] = red[0][tid] + red[1][tid];

    // ---- fused finish: last j-split CTA for this i-tile does bias+sigmoid ----
    __threadfence();
    if (tid == 0) {
        int old = atomicAdd(&g_arrive[blockIdx.x], 1);
        is_last = (old == NSPLIT - 1);
    }
    __syncthreads();
    if (is_last) {
        if (tid < TI) {
            int i = i0 + tid;
            float z = (g_partial[0][i] + g_partial[1][i])
                    + (g_partial[2][i] + g_partial[3][i]) + bias[0];
            out[i] = 1.0f / (1.0f + __expf(-z));
        }
        if (tid == 0) g_arrive[blockIdx.x] = 0;   // reset for next graph replay
    }
}

// ============================================================================
// kernel_launch
// ============================================================================
extern "C" void kernel_launch(void* const* d_in, const int* in_sizes, int n_in,
                              void* d_out, int out_size) {
    const float* x  = (const float*)d_in[0];
    const float* xb = (const float*)d_in[1];
    const float* w  = (const float*)d_in[2];
    const float* b  = (const float*)d_in[3];
    float* out = (float*)d_out;

    prep_kernel<<<512, 256>>>(x, xb, w);
    dim3 grid(KROWS / TI, NSPLIT);
    rbf_main_kernel<<<grid, 256>>>(b, out);
}